// round 4
// baseline (speedup 1.0000x reference)
#include <cuda_runtime.h>
#include <cuda_bf16.h>

#define NG 2048
#define HW 128
#define TANFOV 0.5f
#define NEARP 0.2f
#define AMIN (1.0f/255.0f)
#define LOG2E 1.4426950408889634f
#define TEPS 1e-7f
#define CHUNKS 8
#define CHSZ (NG/CHUNKS)      // 256
#define NCTA 512              // 64 tiles x 8 chunks
#define P1CTA 256             // CTAs doing phase-1 (8 gaussians each)

// depth-sorted per-gaussian data
__device__ float4 g_sa[NG];   // px, py, ca2, cb2
__device__ float4 g_sb[NG];   // cc2, op, cullR2, pad
__device__ float4 g_sc[NG];   // r, g, b, pad
// per-chunk partial (r,g,b,T) per pixel
__device__ float4 g_part[CHUNKS][HW*HW];
// grid barrier state (graph-replay safe: phase is monotonic, count self-resets)
__device__ unsigned g_count;
__device__ unsigned g_phase;

__device__ __forceinline__ float fast_exp2(float x) {
    float r;
    asm("ex2.approx.f32 %0, %1;" : "=f"(r) : "f"(x));
    return r;
}

__device__ __forceinline__ void grid_barrier(unsigned& myphase) {
    __syncthreads();
    if (threadIdx.x == 0) {
        __threadfence();
        unsigned old = atomicAdd(&g_count, 1u);
        if (old == NCTA - 1) {
            g_count = 0;
            __threadfence();
            atomicAdd(&g_phase, 1u);
        } else {
            while (*(volatile unsigned*)&g_phase == myphase) __nanosleep(32);
        }
        __threadfence();
    }
    __syncthreads();
    myphase++;
}

__global__ void __launch_bounds__(256, 4) fused_kernel(
        const float* __restrict__ means3D,
        const float* __restrict__ colors,
        const float* __restrict__ opacities,
        const float* __restrict__ cov3Ds,
        const float* __restrict__ bg,
        float* __restrict__ out_img,
        float* __restrict__ out_radii) {
    // smem union: phase1 uses s_z[2048] (8KB); phase2 uses s_a/s_b/s_c/cnt (10.3KB)
    __shared__ __align__(16) char sraw[10272];
    float*  s_z   = (float*)sraw;
    float4* s_a   = (float4*)sraw;                  // 256*16 = 4096
    float2* s_b   = (float2*)(sraw + 4096);         // 256*8  = 2048
    float4* s_c   = (float4*)(sraw + 6144);         // 256*16 = 4096
    int*    s_cnt = (int*)(sraw + 10240);           // 32
    __shared__ unsigned s_ph;

    int t = threadIdx.x;
    int bx = blockIdx.x;

    if (t == 0) s_ph = *(volatile unsigned*)&g_phase;
    __syncthreads();
    unsigned myphase = s_ph;

    // ================= Phase 1: rank-sort + preprocess =================
    if (bx < P1CTA) {
        // coalesced staging of z = means3D[3j+2]
        for (int idx = t; idx < 3*NG; idx += 256) {
            float v = means3D[idx];
            int q = idx / 3;
            if (idx - q*3 == 2) s_z[q] = v;
        }
        __syncthreads();

        int w = t >> 5, lane = t & 31;
        int i = bx * 8 + w;                 // gaussian for this warp
        float zi = s_z[i];

        int cnt = 0;
        #pragma unroll 8
        for (int j = lane; j < NG; j += 32) {
            float zj = s_z[j];
            cnt += (zj < zi) || (zj == zi && j < i);
        }
        int rank = __reduce_add_sync(0xffffffffu, cnt);

        const float fx = HW / (2.0f * TANFOV);
        const float fy = fx;

        float x = means3D[3*i + 0];
        float y = means3D[3*i + 1];
        float z = zi;
        float invz = 1.0f / z;

        float px = fx * x * invz + 0.5f * HW;
        float py = fy * y * invz + 0.5f * HW;

        const float lim = 1.3f * TANFOV;
        float txn = fminf(fmaxf(x * invz, -lim), lim) * z;
        float tyn = fminf(fmaxf(y * invz, -lim), lim) * z;

        float xx = cov3Ds[6*i+0], xy = cov3Ds[6*i+1], xz = cov3Ds[6*i+2];
        float yy = cov3Ds[6*i+3], yz = cov3Ds[6*i+4], zz = cov3Ds[6*i+5];

        float j00 = fx * invz;
        float j02 = -fx * txn * invz * invz;
        float j11 = fy * invz;
        float j12 = -fy * tyn * invz * invz;

        float M00 = j00*xx + j02*xz;
        float M01 = j00*xy + j02*yz;
        float M02 = j00*xz + j02*zz;
        float M11 = j11*yy + j12*yz;
        float M12 = j11*yz + j12*zz;

        float a = M00*j00 + M02*j02 + 0.3f;
        float b = M01*j11 + M02*j12;
        float c = M11*j11 + M12*j12 + 0.3f;

        float det = a*c - b*b;
        float invdet = 1.0f / det;
        float conA = c * invdet;
        float conB = -b * invdet;
        float conC = a * invdet;

        float mid = 0.5f * (a + c);
        float lam1 = mid + sqrtf(fmaxf(0.1f, mid*mid - det));

        bool valid = (z > NEARP) && (det > 0.0f);
        float radii = valid ? ceilf(3.0f * sqrtf(lam1)) : 0.0f;

        float op = opacities[i];
        float cullR2;
        if (!valid) cullR2 = -1.0f;
        else {
            float tt = op * 255.0f;
            cullR2 = (tt <= 1.0f) ? -1.0f : 2.0f * lam1 * logf(tt);
        }

        float ca2 = -0.5f * LOG2E * conA;
        float cb2 = -LOG2E * conB;
        float cc2 = -0.5f * LOG2E * conC;

        if (lane == 0) {
            out_radii[i] = radii;
            g_sa[rank] = make_float4(px, py, ca2, cb2);
            g_sb[rank] = make_float4(cc2, op, cullR2, 0.0f);
            g_sc[rank] = make_float4(colors[3*i+0], colors[3*i+1], colors[3*i+2], 0.0f);
        }
    }

    grid_barrier(myphase);

    // ================= Phase 2: tiled blend (tile, depth-chunk) =================
    {
        int tile  = bx & 63;
        int chunk = bx >> 6;
        int tx0 = (tile & 7) * 16;
        int ty0 = (tile >> 3) * 16;
        float X = (float)(tx0 + (t & 15));
        float Y = (float)(ty0 + (t >> 4));
        float rx0 = (float)tx0, rx1 = (float)(tx0 + 15);
        float ry0 = (float)ty0, ry1 = (float)(ty0 + 15);

        int lane = t & 31, w = t >> 5;

        int gi = chunk * CHSZ + t;
        float4 A = __ldcg(&g_sa[gi]);
        float4 B = __ldcg(&g_sb[gi]);
        float ddx = fmaxf(0.0f, fmaxf(rx0 - A.x, A.x - rx1));
        float ddy = fmaxf(0.0f, fmaxf(ry0 - A.y, A.y - ry1));
        bool keep = (ddx*ddx + ddy*ddy) <= B.z;   // B.z < 0 => skip

        unsigned bal = __ballot_sync(0xffffffffu, keep);
        if (lane == 0) s_cnt[w] = __popc(bal);
        __syncthreads();

        int off = 0, total = 0;
        #pragma unroll
        for (int k = 0; k < 8; k++) {
            int cn = s_cnt[k];
            off += (k < w) ? cn : 0;
            total += cn;
        }
        int pos = off + __popc(bal & ((1u << lane) - 1u));
        if (keep) {
            s_a[pos] = A;
            s_b[pos] = make_float2(B.x, B.y);
            s_c[pos] = __ldcg(&g_sc[gi]);
        }
        __syncthreads();

        float T = 1.0f, accr = 0.0f, accg = 0.0f, accb = 0.0f;
        for (int j = 0; j < total; j++) {
            if (__ballot_sync(0xffffffffu, T >= TEPS) == 0u) break;
            float4 a = s_a[j];
            float2 bb = s_b[j];
            float4 cc = s_c[j];
            float dx = a.x - X;
            float dy = a.y - Y;
            float p2 = a.z*dx*dx + a.w*dx*dy + bb.x*dy*dy;  // power * log2(e)
            float e = fast_exp2(p2);
            float alpha = fminf(bb.y * e, 0.99f);
            if (p2 > 0.0f || alpha < AMIN) alpha = 0.0f;
            float wgt = alpha * T;
            accr = fmaf(wgt, cc.x, accr);
            accg = fmaf(wgt, cc.y, accg);
            accb = fmaf(wgt, cc.z, accb);
            T = fmaf(-alpha, T, T);
        }

        int p = (ty0 + (t >> 4)) * HW + tx0 + (t & 15);
        g_part[chunk][p] = make_float4(accr, accg, accb, T);
    }

    grid_barrier(myphase);

    // ================= Phase 3: combine =================
    if (bx < 64) {
        int p = bx * 256 + t;
        float T = 1.0f, r = 0.0f, g = 0.0f, b = 0.0f;
        #pragma unroll
        for (int k = 0; k < CHUNKS; k++) {
            float4 c = __ldcg(&g_part[k][p]);
            r = fmaf(T, c.x, r);
            g = fmaf(T, c.y, g);
            b = fmaf(T, c.z, b);
            T *= c.w;
        }
        out_img[p]           = fmaf(T, bg[0], r);
        out_img[HW*HW + p]   = fmaf(T, bg[1], g);
        out_img[2*HW*HW + p] = fmaf(T, bg[2], b);
    }
}

extern "C" void kernel_launch(void* const* d_in, const int* in_sizes, int n_in,
                              void* d_out, int out_size) {
    const float* means3D   = (const float*)d_in[0];
    const float* colors    = (const float*)d_in[1];
    const float* opacities = (const float*)d_in[2];
    const float* cov3Ds    = (const float*)d_in[3];
    const float* bg        = (const float*)d_in[4];
    float* out = (float*)d_out;
    float* out_img   = out;              // 3*128*128
    float* out_radii = out + 3*HW*HW;    // 2048

    fused_kernel<<<NCTA, 256>>>(means3D, colors, opacities, cov3Ds, bg,
                                out_img, out_radii);
}

// round 5
// speedup vs baseline: 1.0380x; 1.0380x over previous
#include <cuda_runtime.h>
#include <cuda_bf16.h>

#define NG 2048
#define HW 128
#define TANFOV 0.5f
#define NEARP 0.2f
#define AMIN (1.0f/255.0f)
#define LOG2E 1.4426950408889634f
#define TEPS 1e-7f
#define CHUNKS 8
#define CHSZ (NG/CHUNKS)      // 256
#define NCTA 512              // 64 tiles x 8 chunks

// depth-sorted per-gaussian data
__device__ float4 g_sa[NG];   // px, py, ca2, cb2
__device__ float4 g_sb[NG];   // cc2, op, cullR2, pad
__device__ float4 g_sc[NG];   // r, g, b, pad
// per-chunk partial (r,g,b,T) per pixel
__device__ float4 g_part[CHUNKS][HW*HW];
// grid barrier state (graph-replay safe: monotonic)
__device__ unsigned g_count;
__device__ unsigned g_phase;
// per-tile arrival counters (monotonic; last arriver of each run sees old%8==7)
__device__ unsigned g_tile_cnt[64];

__device__ __forceinline__ float fast_exp2(float x) {
    float r;
    asm("ex2.approx.f32 %0, %1;" : "=f"(r) : "f"(x));
    return r;
}

__device__ __forceinline__ void grid_barrier(unsigned myphase) {
    __syncthreads();
    if (threadIdx.x == 0) {
        __threadfence();
        unsigned old = atomicAdd(&g_count, 1u);
        if (old == NCTA - 1) {
            g_count = 0;
            __threadfence();
            atomicAdd(&g_phase, 1u);
        } else {
            while (*(volatile unsigned*)&g_phase == myphase) __nanosleep(32);
        }
        __threadfence();
    }
    __syncthreads();
}

__global__ void __launch_bounds__(256, 4) fused_kernel(
        const float* __restrict__ means3D,
        const float* __restrict__ colors,
        const float* __restrict__ opacities,
        const float* __restrict__ cov3Ds,
        const float* __restrict__ bg,
        float* __restrict__ out_img,
        float* __restrict__ out_radii) {
    __shared__ float4 s_a[256];
    __shared__ float2 s_b[256];
    __shared__ float4 s_c[256];
    __shared__ int    s_cnt[8];
    __shared__ unsigned s_ph;

    int t = threadIdx.x;
    int bx = blockIdx.x;
    int w = t >> 5, lane = t & 31;

    if (t == 0) s_ph = *(volatile unsigned*)&g_phase;
    __syncthreads();
    unsigned myphase = s_ph;

    // ===== Phase 1: rank-sort + preprocess, 4 gaussians/CTA (warps 0-3) =====
    if (w < 4) {
        int i = bx * 4 + w;                  // gaussian for this warp
        float zi = __ldg(&means3D[3*i + 2]);

        // stable rank: count z smaller (ties by index), straight from gmem
        int cnt = 0;
        #pragma unroll 8
        for (int j = lane; j < NG; j += 32) {
            float zj = __ldg(&means3D[3*j + 2]);
            cnt += (zj < zi) || (zj == zi && j < i);
        }
        int rank = __reduce_add_sync(0xffffffffu, cnt);

        const float fx = HW / (2.0f * TANFOV);
        const float fy = fx;

        float x = __ldg(&means3D[3*i + 0]);
        float y = __ldg(&means3D[3*i + 1]);
        float z = zi;
        float invz = 1.0f / z;

        float px = fx * x * invz + 0.5f * HW;
        float py = fy * y * invz + 0.5f * HW;

        const float lim = 1.3f * TANFOV;
        float txn = fminf(fmaxf(x * invz, -lim), lim) * z;
        float tyn = fminf(fmaxf(y * invz, -lim), lim) * z;

        float xx = __ldg(&cov3Ds[6*i+0]), xy = __ldg(&cov3Ds[6*i+1]);
        float xz = __ldg(&cov3Ds[6*i+2]), yy = __ldg(&cov3Ds[6*i+3]);
        float yz = __ldg(&cov3Ds[6*i+4]), zz = __ldg(&cov3Ds[6*i+5]);

        float j00 = fx * invz;
        float j02 = -fx * txn * invz * invz;
        float j11 = fy * invz;
        float j12 = -fy * tyn * invz * invz;

        float M00 = j00*xx + j02*xz;
        float M01 = j00*xy + j02*yz;
        float M02 = j00*xz + j02*zz;
        float M11 = j11*yy + j12*yz;
        float M12 = j11*yz + j12*zz;

        float a = M00*j00 + M02*j02 + 0.3f;
        float b = M01*j11 + M02*j12;
        float c = M11*j11 + M12*j12 + 0.3f;

        float det = a*c - b*b;
        float invdet = 1.0f / det;
        float conA = c * invdet;
        float conB = -b * invdet;
        float conC = a * invdet;

        float mid = 0.5f * (a + c);
        float lam1 = mid + sqrtf(fmaxf(0.1f, mid*mid - det));

        bool valid = (z > NEARP) && (det > 0.0f);
        float radii = valid ? ceilf(3.0f * sqrtf(lam1)) : 0.0f;

        float op = __ldg(&opacities[i]);
        float cullR2;
        if (!valid) cullR2 = -1.0f;
        else {
            float tt = op * 255.0f;
            cullR2 = (tt <= 1.0f) ? -1.0f : 2.0f * lam1 * logf(tt);
        }

        float ca2 = -0.5f * LOG2E * conA;
        float cb2 = -LOG2E * conB;
        float cc2 = -0.5f * LOG2E * conC;

        if (lane == 0) {
            out_radii[i] = radii;
            g_sa[rank] = make_float4(px, py, ca2, cb2);
            g_sb[rank] = make_float4(cc2, op, cullR2, 0.0f);
            g_sc[rank] = make_float4(__ldg(&colors[3*i+0]), __ldg(&colors[3*i+1]),
                                     __ldg(&colors[3*i+2]), 0.0f);
        }
    }

    grid_barrier(myphase);

    // ===== Phase 2: tiled blend (tile, depth-chunk) + per-tile combine =====
    int tile  = bx & 63;
    int chunk = bx >> 6;
    int tx0 = (tile & 7) * 16;
    int ty0 = (tile >> 3) * 16;
    float X = (float)(tx0 + (t & 15));
    float Y = (float)(ty0 + (t >> 4));
    float rx0 = (float)tx0, rx1 = (float)(tx0 + 15);
    float ry0 = (float)ty0, ry1 = (float)(ty0 + 15);

    int gi = chunk * CHSZ + t;
    float4 A = __ldcg(&g_sa[gi]);
    float4 B = __ldcg(&g_sb[gi]);
    float ddx = fmaxf(0.0f, fmaxf(rx0 - A.x, A.x - rx1));
    float ddy = fmaxf(0.0f, fmaxf(ry0 - A.y, A.y - ry1));
    bool keep = (ddx*ddx + ddy*ddy) <= B.z;   // B.z < 0 => skip

    unsigned bal = __ballot_sync(0xffffffffu, keep);
    if (lane == 0) s_cnt[w] = __popc(bal);
    __syncthreads();

    int off = 0, total = 0;
    #pragma unroll
    for (int k = 0; k < 8; k++) {
        int cn = s_cnt[k];
        off += (k < w) ? cn : 0;
        total += cn;
    }
    int pos = off + __popc(bal & ((1u << lane) - 1u));
    if (keep) {
        s_a[pos] = A;
        s_b[pos] = make_float2(B.x, B.y);
        s_c[pos] = __ldcg(&g_sc[gi]);
    }
    __syncthreads();

    float T = 1.0f, accr = 0.0f, accg = 0.0f, accb = 0.0f;
    for (int j = 0; j < total; j++) {
        if (__ballot_sync(0xffffffffu, T >= TEPS) == 0u) break;
        float4 a = s_a[j];
        float2 bb = s_b[j];
        float4 cc = s_c[j];
        float dx = a.x - X;
        float dy = a.y - Y;
        float p2 = a.z*dx*dx + a.w*dx*dy + bb.x*dy*dy;  // power * log2(e)
        float e = fast_exp2(p2);
        float alpha = fminf(bb.y * e, 0.99f);
        if (p2 > 0.0f || alpha < AMIN) alpha = 0.0f;
        float wgt = alpha * T;
        accr = fmaf(wgt, cc.x, accr);
        accg = fmaf(wgt, cc.y, accg);
        accb = fmaf(wgt, cc.z, accb);
        T = fmaf(-alpha, T, T);
    }

    int p = (ty0 + (t >> 4)) * HW + tx0 + (t & 15);
    g_part[chunk][p] = make_float4(accr, accg, accb, T);

    // last arriving chunk-CTA of this tile folds the 8 partials
    __syncthreads();
    __shared__ unsigned s_last;
    if (t == 0) {
        __threadfence();
        unsigned old = atomicAdd(&g_tile_cnt[tile], 1u);
        s_last = ((old & 7u) == 7u) ? 1u : 0u;
    }
    __syncthreads();

    if (s_last) {
        __threadfence();   // acquire: make all 8 partials visible
        float Tc = 1.0f, r = 0.0f, g = 0.0f, b = 0.0f;
        #pragma unroll
        for (int k = 0; k < CHUNKS; k++) {
            float4 c = __ldcg(&g_part[k][p]);
            r = fmaf(Tc, c.x, r);
            g = fmaf(Tc, c.y, g);
            b = fmaf(Tc, c.z, b);
            Tc *= c.w;
        }
        out_img[p]           = fmaf(Tc, bg[0], r);
        out_img[HW*HW + p]   = fmaf(Tc, bg[1], g);
        out_img[2*HW*HW + p] = fmaf(Tc, bg[2], b);
    }
}

extern "C" void kernel_launch(void* const* d_in, const int* in_sizes, int n_in,
                              void* d_out, int out_size) {
    const float* means3D   = (const float*)d_in[0];
    const float* colors    = (const float*)d_in[1];
    const float* opacities = (const float*)d_in[2];
    const float* cov3Ds    = (const float*)d_in[3];
    const float* bg        = (const float*)d_in[4];
    float* out = (float*)d_out;
    float* out_img   = out;              // 3*128*128
    float* out_radii = out + 3*HW*HW;    // 2048

    fused_kernel<<<NCTA, 256>>>(means3D, colors, opacities, cov3Ds, bg,
                                out_img, out_radii);
}